// round 1
// baseline (speedup 1.0000x reference)
#include <cuda_runtime.h>
#include <math.h>

// Problem constants (B=4, S=2048, H=768, F=3072, E=8, TOP_K=2)
#define NTOK 8192
#define HD   768
#define FD   3072
#define NEXP 8

// ---------------- Scratch (static device globals — no runtime allocation) ----
__device__ int   g_counts[NEXP];
__device__ int   g_offs[NEXP + 1];
__device__ int   g_cursor[NEXP];
__device__ int   g_topk_idx[NTOK * 2];
__device__ float g_topk_w[NTOK * 2];
__device__ int   g_assign_tok[NTOK * 2];   // per assignment row: source token
__device__ int   g_pos_of[NTOK * 2];       // per (token, k): assignment row
__device__ float g_hbuf[(size_t)NTOK * 2 * FD];  // GEMM1 output (201 MB)
__device__ float g_buf2[(size_t)NTOK * 2 * HD];  // GEMM2 output (50 MB)

// ---------------- Step 1: zero per-launch state ------------------------------
__global__ void zero_counts_kernel() {
    if (threadIdx.x < NEXP) g_counts[threadIdx.x] = 0;
}

// ---------------- Step 2: router (logits, top-2, softmax, counts) ------------
// One warp per token. Wr (8x768 = 24 KB) staged in shared memory.
__global__ void router_kernel(const float* __restrict__ x,
                              const float* __restrict__ Wr) {
    __shared__ float sWr[NEXP * HD];
    int tid = threadIdx.x;
    for (int i = tid; i < NEXP * HD; i += blockDim.x) sWr[i] = Wr[i];
    __syncthreads();

    int warp = tid >> 5, lane = tid & 31;
    int t = blockIdx.x * (blockDim.x >> 5) + warp;
    if (t >= NTOK) return;

    const float* xr = x + (size_t)t * HD;
    float acc[NEXP];
#pragma unroll
    for (int e = 0; e < NEXP; e++) acc[e] = 0.f;

    for (int h = lane; h < HD; h += 32) {
        float xv = xr[h];
#pragma unroll
        for (int e = 0; e < NEXP; e++)
            acc[e] = fmaf(xv, sWr[e * HD + h], acc[e]);
    }
#pragma unroll
    for (int e = 0; e < NEXP; e++) {
#pragma unroll
        for (int o = 16; o > 0; o >>= 1)
            acc[e] += __shfl_xor_sync(0xFFFFFFFFu, acc[e], o);
    }

    if (lane == 0) {
        // top-1 (first index on ties, matching jax.lax.top_k)
        int i0 = 0; float v0 = acc[0];
#pragma unroll
        for (int e = 1; e < NEXP; e++)
            if (acc[e] > v0) { v0 = acc[e]; i0 = e; }
        // top-2
        int i1 = -1; float v1 = -3.4e38f;
#pragma unroll
        for (int e = 0; e < NEXP; e++)
            if (e != i0 && acc[e] > v1) { v1 = acc[e]; i1 = e; }

        float z = expf(v1 - v0);       // v1 <= v0
        float inv = 1.f / (1.f + z);
        g_topk_idx[2 * t]     = i0;
        g_topk_idx[2 * t + 1] = i1;
        g_topk_w[2 * t]     = inv;
        g_topk_w[2 * t + 1] = z * inv;
        atomicAdd(&g_counts[i0], 1);
        atomicAdd(&g_counts[i1], 1);
    }
}

// ---------------- Step 3: exclusive scan over 8 experts ----------------------
__global__ void offsets_kernel() {
    int acc = 0;
    for (int e = 0; e < NEXP; e++) {
        g_offs[e] = acc;
        g_cursor[e] = acc;
        acc += g_counts[e];
    }
    g_offs[NEXP] = acc;   // == NTOK*2
}

// ---------------- Step 4: build per-expert token lists -----------------------
__global__ void fill_kernel() {
    int i = blockIdx.x * blockDim.x + threadIdx.x;
    if (i >= NTOK * 2) return;
    int e = g_topk_idx[i];
    int pos = atomicAdd(&g_cursor[e], 1);
    g_assign_tok[pos] = i >> 1;
    g_pos_of[i] = pos;
}

// ---------------- Steps 5/6: grouped GEMM ------------------------------------
// C[m, n] = sum_k A[m, k] * W_e[n, k] + bias_e[n]   (both operands K-major)
// FIRST=true : A = x rows gathered via g_assign_tok, C = g_hbuf, GELU epilogue
// FIRST=false: A = g_hbuf rows (assignment order),  C = g_buf2, plain epilogue
// 128x128 tile, BK=16, 256 threads, 8x8 per thread.
template <bool FIRST>
__global__ void __launch_bounds__(256, 2)
moe_gemm_kernel(const float* __restrict__ Xin,
                const float* __restrict__ W,
                const float* __restrict__ bias) {
    constexpr int KD = FIRST ? HD : FD;
    constexpr int ND = FIRST ? FD : HD;

    const int e = blockIdx.z;
    const int segStart = g_offs[e];
    const int nRows = g_offs[e + 1] - segStart;
    const int rowBase = blockIdx.y * 128;
    if (rowBase >= nRows) return;
    const int colBase = blockIdx.x * 128;

    const float* __restrict__ A = FIRST ? Xin : g_hbuf;
    float* __restrict__ C = FIRST ? g_hbuf : g_buf2;
    const float* Wb = W + (size_t)e * ND * KD;
    const float* biasE = bias + e * ND + colBase;

    __shared__ float As[16][128];
    __shared__ float Bs[16][128];

    const int tid = threadIdx.x;
    const int tx = tid & 15, ty = tid >> 4;
    const int lr = tid >> 2;           // 0..63
    const int lk = (tid & 3) << 2;     // 0,4,8,12

    const int r0 = rowBase + lr, r1 = r0 + 64;
    const bool v0 = r0 < nRows, v1 = r1 < nRows;
    size_t arow0 = 0, arow1 = 0;
    if (FIRST) {
        if (v0) arow0 = (size_t)g_assign_tok[segStart + r0];
        if (v1) arow1 = (size_t)g_assign_tok[segStart + r1];
    } else {
        arow0 = (size_t)(segStart + r0);
        arow1 = (size_t)(segStart + (v1 ? r1 : r0));
    }
    const float* ap0 = A + arow0 * KD + lk;
    const float* ap1 = A + arow1 * KD + lk;
    const float* bp0 = Wb + (size_t)(colBase + lr) * KD + lk;
    const float* bp1 = bp0 + (size_t)64 * KD;

    float c[8][8];
#pragma unroll
    for (int i = 0; i < 8; i++)
#pragma unroll
        for (int j = 0; j < 8; j++) c[i][j] = 0.f;

    for (int kt = 0; kt < KD; kt += 16) {
        float4 a0 = v0 ? *(const float4*)(ap0 + kt) : make_float4(0.f, 0.f, 0.f, 0.f);
        float4 a1 = v1 ? *(const float4*)(ap1 + kt) : make_float4(0.f, 0.f, 0.f, 0.f);
        float4 b0 = *(const float4*)(bp0 + kt);
        float4 b1 = *(const float4*)(bp1 + kt);

        __syncthreads();
        As[lk + 0][lr] = a0.x; As[lk + 1][lr] = a0.y;
        As[lk + 2][lr] = a0.z; As[lk + 3][lr] = a0.w;
        As[lk + 0][lr + 64] = a1.x; As[lk + 1][lr + 64] = a1.y;
        As[lk + 2][lr + 64] = a1.z; As[lk + 3][lr + 64] = a1.w;
        Bs[lk + 0][lr] = b0.x; Bs[lk + 1][lr] = b0.y;
        Bs[lk + 2][lr] = b0.z; Bs[lk + 3][lr] = b0.w;
        Bs[lk + 0][lr + 64] = b1.x; Bs[lk + 1][lr + 64] = b1.y;
        Bs[lk + 2][lr + 64] = b1.z; Bs[lk + 3][lr + 64] = b1.w;
        __syncthreads();

#pragma unroll
        for (int kk = 0; kk < 16; kk++) {
            float ar[8], br[8];
            *(float4*)(ar)     = *(const float4*)&As[kk][ty * 8];
            *(float4*)(ar + 4) = *(const float4*)&As[kk][ty * 8 + 4];
            *(float4*)(br)     = *(const float4*)&Bs[kk][tx * 8];
            *(float4*)(br + 4) = *(const float4*)&Bs[kk][tx * 8 + 4];
#pragma unroll
            for (int i = 0; i < 8; i++)
#pragma unroll
                for (int j = 0; j < 8; j++)
                    c[i][j] = fmaf(ar[i], br[j], c[i][j]);
        }
    }

    // Epilogue: bias (+ exact-erf GELU for GEMM1), vectorized stores.
#pragma unroll
    for (int i = 0; i < 8; i++) {
        int row = rowBase + ty * 8 + i;
        if (row >= nRows) continue;
        float* cp = C + (size_t)(segStart + row) * ND + colBase + tx * 8;
        float outv[8];
#pragma unroll
        for (int j = 0; j < 8; j++) {
            float v = c[i][j] + biasE[tx * 8 + j];
            if (FIRST)
                v = 0.5f * v * (1.f + erff(v * 0.70710678118654752f));
            outv[j] = v;
        }
        *(float4*)cp       = *(float4*)(outv);
        *(float4*)(cp + 4) = *(float4*)(outv + 4);
    }
}

// ---------------- Step 7: weighted combine of the two expert outputs ---------
__global__ void combine_kernel(float* __restrict__ out) {
    const int HV = HD / 4;   // float4s per token row
    int idx = blockIdx.x * blockDim.x + threadIdx.x;
    if (idx >= NTOK * HV) return;
    int t = idx / HV;
    int h4 = (idx - t * HV) * 4;
    float w0 = g_topk_w[2 * t], w1 = g_topk_w[2 * t + 1];
    int p0 = g_pos_of[2 * t], p1 = g_pos_of[2 * t + 1];
    float4 a = *(const float4*)&g_buf2[(size_t)p0 * HD + h4];
    float4 b = *(const float4*)&g_buf2[(size_t)p1 * HD + h4];
    float4 o;
    o.x = w0 * a.x + w1 * b.x;
    o.y = w0 * a.y + w1 * b.y;
    o.z = w0 * a.z + w1 * b.z;
    o.w = w0 * a.w + w1 * b.w;
    *(float4*)&out[(size_t)t * HD + h4] = o;
}

// ---------------- Launch ------------------------------------------------------
extern "C" void kernel_launch(void* const* d_in, const int* in_sizes, int n_in,
                              void* d_out, int out_size) {
    const float* x  = (const float*)d_in[0];   // [8192, 768]
    const float* Wr = (const float*)d_in[1];   // [8, 768]
    const float* Wi = (const float*)d_in[2];   // [8, 3072, 768]
    const float* bi = (const float*)d_in[3];   // [8, 3072]
    const float* Wo = (const float*)d_in[4];   // [8, 768, 3072]
    const float* bo = (const float*)d_in[5];   // [8, 768]
    float* out = (float*)d_out;                // [8192, 768]

    zero_counts_kernel<<<1, 32>>>();
    router_kernel<<<NTOK / 8, 256>>>(x, Wr);           // 8 warps = 8 tokens/block
    offsets_kernel<<<1, 1>>>();
    fill_kernel<<<(NTOK * 2 + 255) / 256, 256>>>();

    {   // GEMM1: [16384, 768] x [3072, 768]^T -> g_hbuf (GELU)
        dim3 grid(FD / 128, NTOK / 128, NEXP);         // 24 x 64 x 8
        moe_gemm_kernel<true><<<grid, 256>>>(x, Wi, bi);
    }
    {   // GEMM2: [16384, 3072] x [768, 3072]^T -> g_buf2
        dim3 grid(HD / 128, NTOK / 128, NEXP);         // 6 x 64 x 8
        moe_gemm_kernel<false><<<grid, 256>>>(nullptr, Wo, bo);
    }
    combine_kernel<<<(NTOK * (HD / 4) + 255) / 256, 256>>>(out);
}

// round 3
// speedup vs baseline: 1.6831x; 1.6831x over previous
#include <cuda_runtime.h>
#include <cuda_bf16.h>
#include <math.h>
#include <stdint.h>

// Problem constants (B=4, S=2048, H=768, F=3072, E=8, TOP_K=2)
#define NTOK 8192
#define HD   768
#define FD   3072
#define NEXP 8
#define NASSIGN (NTOK * 2)

// ---------------- Scratch (static device globals) ----------------------------
__device__ int   g_counts[NEXP];
__device__ int   g_offs[NEXP + 1];
__device__ int   g_cursor[NEXP];
__device__ int   g_topk_idx[NASSIGN];
__device__ float g_topk_w[NASSIGN];
__device__ int   g_assign_tok[NASSIGN];
__device__ int   g_pos_of[NASSIGN];
__device__ int   g_tile_e[160];
__device__ int   g_tile_r[160];
__device__ int   g_ntiles;

__device__ __align__(16) __nv_bfloat16 g_xhi[NTOK * HD];
__device__ __align__(16) __nv_bfloat16 g_xlo[NTOK * HD];
__device__ __align__(16) __nv_bfloat16 g_Wihi[NEXP * FD * HD];
__device__ __align__(16) __nv_bfloat16 g_Wilo[NEXP * FD * HD];
__device__ __align__(16) __nv_bfloat16 g_Wohi[NEXP * HD * FD];
__device__ __align__(16) __nv_bfloat16 g_Wolo[NEXP * HD * FD];
__device__ __align__(16) __nv_bfloat16 g_hhi[(size_t)NASSIGN * FD];
__device__ __align__(16) __nv_bfloat16 g_hlo[(size_t)NASSIGN * FD];
__device__ __align__(16) float         g_buf2[(size_t)NASSIGN * HD];

// ---------------- PTX helpers -------------------------------------------------
__device__ __forceinline__ uint32_t smem_to_u32(const void* p) {
    uint32_t a;
    asm("{ .reg .u64 t; cvta.to.shared.u64 t, %1; cvt.u32.u64 %0, t; }" : "=r"(a) : "l"(p));
    return a;
}
__device__ __forceinline__ void cp16(uint32_t dst, const void* src, int sz) {
    asm volatile("cp.async.cg.shared.global [%0], [%1], 16, %2;"
                 :: "r"(dst), "l"(src), "r"(sz) : "memory");
}
#define CP_COMMIT() asm volatile("cp.async.commit_group;" ::: "memory")
#define CP_WAIT0()  asm volatile("cp.async.wait_group 0;" ::: "memory")
#define CP_WAIT1()  asm volatile("cp.async.wait_group 1;" ::: "memory")

#define LDSM4(r0, r1, r2, r3, addr) \
    asm volatile("ldmatrix.sync.aligned.m8n8.x4.shared.b16 {%0,%1,%2,%3}, [%4];" \
                 : "=r"(r0), "=r"(r1), "=r"(r2), "=r"(r3) : "r"(addr))

__device__ __forceinline__ void mma16816(float* d, const uint32_t* a, const uint32_t* b) {
    asm volatile(
        "mma.sync.aligned.m16n8k16.row.col.f32.bf16.bf16.f32 "
        "{%0,%1,%2,%3}, {%4,%5,%6,%7}, {%8,%9}, {%0,%1,%2,%3};"
        : "+f"(d[0]), "+f"(d[1]), "+f"(d[2]), "+f"(d[3])
        : "r"(a[0]), "r"(a[1]), "r"(a[2]), "r"(a[3]), "r"(b[0]), "r"(b[1]));
}

// ---------------- Small kernels (routing) ------------------------------------
__global__ void zero_counts_kernel() {
    if (threadIdx.x < NEXP) g_counts[threadIdx.x] = 0;
}

__global__ void router_kernel(const float* __restrict__ x, const float* __restrict__ Wr) {
    __shared__ float sWr[NEXP * HD];
    int tid = threadIdx.x;
    for (int i = tid; i < NEXP * HD; i += blockDim.x) sWr[i] = Wr[i];
    __syncthreads();

    int warp = tid >> 5, lane = tid & 31;
    int t = blockIdx.x * (blockDim.x >> 5) + warp;
    if (t >= NTOK) return;

    const float* xr = x + (size_t)t * HD;
    float acc[NEXP];
#pragma unroll
    for (int e = 0; e < NEXP; e++) acc[e] = 0.f;
    for (int h = lane; h < HD; h += 32) {
        float xv = xr[h];
#pragma unroll
        for (int e = 0; e < NEXP; e++) acc[e] = fmaf(xv, sWr[e * HD + h], acc[e]);
    }
#pragma unroll
    for (int e = 0; e < NEXP; e++)
#pragma unroll
        for (int o = 16; o > 0; o >>= 1) acc[e] += __shfl_xor_sync(0xFFFFFFFFu, acc[e], o);

    if (lane == 0) {
        int i0 = 0; float v0 = acc[0];
#pragma unroll
        for (int e = 1; e < NEXP; e++) if (acc[e] > v0) { v0 = acc[e]; i0 = e; }
        int i1 = -1; float v1 = -3.4e38f;
#pragma unroll
        for (int e = 0; e < NEXP; e++) if (e != i0 && acc[e] > v1) { v1 = acc[e]; i1 = e; }
        float z = expf(v1 - v0);
        float inv = 1.f / (1.f + z);
        g_topk_idx[2 * t] = i0;     g_topk_idx[2 * t + 1] = i1;
        g_topk_w[2 * t] = inv;      g_topk_w[2 * t + 1] = z * inv;
        atomicAdd(&g_counts[i0], 1);
        atomicAdd(&g_counts[i1], 1);
    }
}

__global__ void offsets_tiles_kernel() {
    int acc = 0, nt = 0;
    for (int e = 0; e < NEXP; e++) {
        g_offs[e] = acc; g_cursor[e] = acc;
        int c = g_counts[e];
        for (int r = 0; r < c; r += 128) { g_tile_e[nt] = e; g_tile_r[nt] = r; nt++; }
        acc += c;
    }
    g_offs[NEXP] = acc;
    g_ntiles = nt;
}

__global__ void fill_kernel() {
    int i = blockIdx.x * blockDim.x + threadIdx.x;
    if (i >= NASSIGN) return;
    int e = g_topk_idx[i];
    int pos = atomicAdd(&g_cursor[e], 1);
    g_assign_tok[pos] = i >> 1;
    g_pos_of[i] = pos;
}

// ---------------- fp32 -> (bf16 hi, bf16 lo) split ---------------------------
__global__ void split_kernel(const float4* __restrict__ src,
                             __nv_bfloat162* __restrict__ hi,
                             __nv_bfloat162* __restrict__ lo, int n4) {
    int i = blockIdx.x * blockDim.x + threadIdx.x;
    if (i >= n4) return;
    float4 v = src[i];
    __nv_bfloat16 h0 = __float2bfloat16(v.x), h1 = __float2bfloat16(v.y);
    __nv_bfloat16 h2 = __float2bfloat16(v.z), h3 = __float2bfloat16(v.w);
    __nv_bfloat16 l0 = __float2bfloat16(v.x - __bfloat162float(h0));
    __nv_bfloat16 l1 = __float2bfloat16(v.y - __bfloat162float(h1));
    __nv_bfloat16 l2 = __float2bfloat16(v.z - __bfloat162float(h2));
    __nv_bfloat16 l3 = __float2bfloat16(v.w - __bfloat162float(h3));
    hi[2 * i]     = __halves2bfloat162(h0, h1);
    hi[2 * i + 1] = __halves2bfloat162(h2, h3);
    lo[2 * i]     = __halves2bfloat162(l0, l1);
    lo[2 * i + 1] = __halves2bfloat162(l2, l3);
}

// ---------------- HMMA grouped GEMM ------------------------------------------
// C[128, 128] fp32 accum = 3-pass bf16 split product:
//   A_hi@B_hi + A_hi@B_lo + A_lo@B_hi  (passes appended to the K loop)
// A rows gathered per expert segment; B = expert weights, both K-major.
// BK=64 bf16 (128B rows, SW128 xor swizzle), cp.async double buffer,
// 8 warps (2x4), warp tile 64x32, mma.sync.m16n8k16 bf16.
#define GEMM_SMEM_BYTES 65536

template <bool FIRST>
__global__ void __launch_bounds__(256, 1)
moe_hmma_kernel(const float* __restrict__ bias) {
    constexpr int KD = FIRST ? HD : FD;
    constexpr int ND = FIRST ? FD : HD;
    constexpr int BK = 64;
    constexpr int NKT = KD / BK;
    constexpr int NIT = 3 * NKT;
    constexpr int STAGE = 32768;   // bytes per stage (A 16KB + B 16KB)

    const int tileIdx = blockIdx.y;
    if (tileIdx >= g_ntiles) return;
    const int e = g_tile_e[tileIdx];
    const int rowBase = g_tile_r[tileIdx];
    const int segStart = g_offs[e];
    const int nRows = g_offs[e + 1] - segStart;
    const int colBase = blockIdx.x * 128;

    extern __shared__ char smem[];
    const uint32_t sbase = smem_to_u32(smem);

    const int tid = threadIdx.x;
    const int wid = tid >> 5, lane = tid & 31;

    // ---- cp.async load addressing: thread -> (row = tid/2, half = tid&1) ----
    const int lrow = tid >> 1;
    const int half = tid & 1;
    bool av;
    const __nv_bfloat16 *aHiP, *aLoP, *bHiP, *bLoP;
    {
        int r = rowBase + lrow;
        av = r < nRows;
        size_t arow = 0;
        if (av) arow = FIRST ? (size_t)g_assign_tok[segStart + r] : (size_t)(segStart + r);
        size_t aoff = arow * KD;
        aHiP = (FIRST ? g_xhi : g_hhi) + aoff;
        aLoP = (FIRST ? g_xlo : g_hlo) + aoff;
        size_t brow = ((size_t)e * ND + colBase + lrow) * KD;
        bHiP = (FIRST ? g_Wihi : g_Wohi) + brow;
        bLoP = (FIRST ? g_Wilo : g_Wolo) + brow;
    }
    uint32_t dstOff[4];
    {
        const uint32_t rmask = (lrow & 7) << 4;
#pragma unroll
        for (int i = 0; i < 4; i++) {
            uint32_t kb = (uint32_t)(half * 4 + i) * 16;
            dstOff[i] = (uint32_t)lrow * 128 + (kb ^ rmask);
        }
    }
    const int aSz = av ? 16 : 0;

    auto load_stage = [&](int buf, int it) {
        const int pass = it / NKT;
        const int kt = it - pass * NKT;
        const __nv_bfloat16* aP = (pass < 2) ? aHiP : aLoP;
        const __nv_bfloat16* bP = (pass == 1) ? bLoP : bHiP;
        const char* aS = (const char*)(aP + kt * BK) + half * 64;
        const char* bS = (const char*)(bP + kt * BK) + half * 64;
        const uint32_t aD = sbase + buf * STAGE;
        const uint32_t bD = aD + 16384;
#pragma unroll
        for (int i = 0; i < 4; i++) cp16(aD + dstOff[i], aS + i * 16, aSz);
#pragma unroll
        for (int i = 0; i < 4; i++) cp16(bD + dstOff[i], bS + i * 16, 16);
        CP_COMMIT();
    };

    // ---- ldmatrix addressing (per warp) ----
    const int wm = wid & 1;        // 2 m-blocks of 64
    const int wn = wid >> 1;       // 4 n-blocks of 32
    const int warpM = wm * 64;
    const int warpN = wn * 32;

    uint32_t aRowB[4], aMask[4];
#pragma unroll
    for (int mi = 0; mi < 4; mi++) {
        int row = warpM + mi * 16 + (lane & 7) + ((lane >> 3) & 1) * 8;
        aRowB[mi] = (uint32_t)row * 128;
        aMask[mi] = (uint32_t)(row & 7) << 4;
    }
    const uint32_t aKadd = ((lane >> 4) & 1) * 16;   // k8 half -> +16B

    uint32_t bRowB[2], bMask[2];
#pragma unroll
    for (int np = 0; np < 2; np++) {
        int row = warpN + np * 16 + (lane & 7) + ((lane >> 4) & 1) * 8;
        bRowB[np] = (uint32_t)row * 128;
        bMask[np] = (uint32_t)(row & 7) << 4;
    }
    const uint32_t bKadd = ((lane >> 3) & 1) * 16;

    float acc[4][4][4];
#pragma unroll
    for (int mi = 0; mi < 4; mi++)
#pragma unroll
        for (int ni = 0; ni < 4; ni++)
#pragma unroll
            for (int k = 0; k < 4; k++) acc[mi][ni][k] = 0.f;

    // ---- pipelined mainloop ----
    load_stage(0, 0);
    for (int it = 0; it < NIT; ++it) {
        const int buf = it & 1;
        if (it + 1 < NIT) { load_stage(buf ^ 1, it + 1); CP_WAIT1(); }
        else              { CP_WAIT0(); }
        __syncthreads();

        const uint32_t Ab = sbase + buf * STAGE;
        const uint32_t Bb = Ab + 16384;
#pragma unroll
        for (int kk = 0; kk < 4; kk++) {
            const uint32_t kbyte = (uint32_t)kk * 32;
            uint32_t af[4][4];
#pragma unroll
            for (int mi = 0; mi < 4; mi++)
                LDSM4(af[mi][0], af[mi][1], af[mi][2], af[mi][3],
                      Ab + aRowB[mi] + ((kbyte + aKadd) ^ aMask[mi]));
            uint32_t bfr[2][4];
#pragma unroll
            for (int np = 0; np < 2; np++)
                LDSM4(bfr[np][0], bfr[np][1], bfr[np][2], bfr[np][3],
                      Bb + bRowB[np] + ((kbyte + bKadd) ^ bMask[np]));
#pragma unroll
            for (int mi = 0; mi < 4; mi++)
#pragma unroll
                for (int ni = 0; ni < 4; ni++)
                    mma16816(acc[mi][ni], af[mi], &bfr[ni >> 1][2 * (ni & 1)]);
        }
        __syncthreads();
    }

    // ---- epilogue: bias (+GELU+split for GEMM1) ------------------------------
    const float* bE = bias + (size_t)e * ND + colBase;
    const int qrow = lane >> 2;            // 0..7
    const int qcol = 2 * (lane & 3);       // 0,2,4,6
#pragma unroll
    for (int mi = 0; mi < 4; mi++) {
#pragma unroll
        for (int half2 = 0; half2 < 2; half2++) {
            int row = rowBase + warpM + mi * 16 + qrow + half2 * 8;
            if (row >= nRows) continue;
            size_t orow = (size_t)segStart + row;
#pragma unroll
            for (int ni = 0; ni < 4; ni++) {
                int col = colBase + warpN + ni * 8 + qcol;
                float v0 = acc[mi][ni][2 * half2]     + bE[warpN + ni * 8 + qcol];
                float v1 = acc[mi][ni][2 * half2 + 1] + bE[warpN + ni * 8 + qcol + 1];
                if (FIRST) {
                    v0 = 0.5f * v0 * (1.f + erff(v0 * 0.70710678118654752f));
                    v1 = 0.5f * v1 * (1.f + erff(v1 * 0.70710678118654752f));
                    __nv_bfloat16 h0 = __float2bfloat16(v0);
                    __nv_bfloat16 h1 = __float2bfloat16(v1);
                    __nv_bfloat16 l0 = __float2bfloat16(v0 - __bfloat162float(h0));
                    __nv_bfloat16 l1 = __float2bfloat16(v1 - __bfloat162float(h1));
                    *(__nv_bfloat162*)(g_hhi + orow * FD + col) = __halves2bfloat162(h0, h1);
                    *(__nv_bfloat162*)(g_hlo + orow * FD + col) = __halves2bfloat162(l0, l1);
                } else {
                    float2 o = make_float2(v0, v1);
                    *(float2*)(g_buf2 + orow * HD + col) = o;
                }
            }
        }
    }
}

// ---------------- Combine -----------------------------------------------------
__global__ void combine_kernel(float* __restrict__ out) {
    const int HV = HD / 4;
    int idx = blockIdx.x * blockDim.x + threadIdx.x;
    if (idx >= NTOK * HV) return;
    int t = idx / HV;
    int h4 = (idx - t * HV) * 4;
    float w0 = g_topk_w[2 * t], w1 = g_topk_w[2 * t + 1];
    int p0 = g_pos_of[2 * t], p1 = g_pos_of[2 * t + 1];
    float4 a = *(const float4*)&g_buf2[(size_t)p0 * HD + h4];
    float4 b = *(const float4*)&g_buf2[(size_t)p1 * HD + h4];
    float4 o;
    o.x = w0 * a.x + w1 * b.x;
    o.y = w0 * a.y + w1 * b.y;
    o.z = w0 * a.z + w1 * b.z;
    o.w = w0 * a.w + w1 * b.w;
    *(float4*)&out[(size_t)t * HD + h4] = o;
}

// ---------------- Launch ------------------------------------------------------
extern "C" void kernel_launch(void* const* d_in, const int* in_sizes, int n_in,
                              void* d_out, int out_size) {
    const float* x  = (const float*)d_in[0];   // [8192, 768]
    const float* Wr = (const float*)d_in[1];   // [8, 768]
    const float* Wi = (const float*)d_in[2];   // [8, 3072, 768]
    const float* bi = (const float*)d_in[3];   // [8, 3072]
    const float* Wo = (const float*)d_in[4];   // [8, 768, 3072]
    const float* bo = (const float*)d_in[5];   // [8, 768]
    float* out = (float*)d_out;                // [8192, 768]

    cudaFuncSetAttribute(moe_hmma_kernel<true>,
                         cudaFuncAttributeMaxDynamicSharedMemorySize, GEMM_SMEM_BYTES);
    cudaFuncSetAttribute(moe_hmma_kernel<false>,
                         cudaFuncAttributeMaxDynamicSharedMemorySize, GEMM_SMEM_BYTES);

    __nv_bfloat16 *p_xhi, *p_xlo, *p_Wihi, *p_Wilo, *p_Wohi, *p_Wolo;
    cudaGetSymbolAddress((void**)&p_xhi,  g_xhi);
    cudaGetSymbolAddress((void**)&p_xlo,  g_xlo);
    cudaGetSymbolAddress((void**)&p_Wihi, g_Wihi);
    cudaGetSymbolAddress((void**)&p_Wilo, g_Wilo);
    cudaGetSymbolAddress((void**)&p_Wohi, g_Wohi);
    cudaGetSymbolAddress((void**)&p_Wolo, g_Wolo);

    zero_counts_kernel<<<1, 32>>>();
    router_kernel<<<NTOK / 8, 256>>>(x, Wr);
    offsets_tiles_kernel<<<1, 1>>>();
    fill_kernel<<<(NASSIGN + 255) / 256, 256>>>();

    {   // fp32 -> bf16 hi/lo splits
        int n4 = NTOK * HD / 4;
        split_kernel<<<(n4 + 255) / 256, 256>>>((const float4*)x,
                                                (__nv_bfloat162*)p_xhi, (__nv_bfloat162*)p_xlo, n4);
        n4 = NEXP * FD * HD / 4;
        split_kernel<<<(n4 + 255) / 256, 256>>>((const float4*)Wi,
                                                (__nv_bfloat162*)p_Wihi, (__nv_bfloat162*)p_Wilo, n4);
        split_kernel<<<(n4 + 255) / 256, 256>>>((const float4*)Wo,
                                                (__nv_bfloat162*)p_Wohi, (__nv_bfloat162*)p_Wolo, n4);
    }

    {   // GEMM1: [rows, 768] @ Wi^T -> h (GELU + hi/lo bf16 split)
        dim3 grid(FD / 128, 136, 1);
        moe_hmma_kernel<true><<<grid, 256, GEMM_SMEM_BYTES>>>(bi);
    }
    {   // GEMM2: [rows, 3072] @ Wo^T -> g_buf2 (fp32)
        dim3 grid(HD / 128, 136, 1);
        moe_hmma_kernel<false><<<grid, 256, GEMM_SMEM_BYTES>>>(bo);
    }
    combine_kernel<<<(NTOK * (HD / 4) + 255) / 256, 256>>>(out);
}

// round 4
// speedup vs baseline: 1.9074x; 1.1333x over previous
#include <cuda_runtime.h>
#include <cuda_bf16.h>
#include <math.h>
#include <stdint.h>

// Problem constants (B=4, S=2048, H=768, F=3072, E=8, TOP_K=2)
#define NTOK 8192
#define HD   768
#define FD   3072
#define NEXP 8
#define NASSIGN (NTOK * 2)

// ---------------- Scratch (static device globals) ----------------------------
__device__ int   g_counts[NEXP];
__device__ int   g_relcur[NEXP];
__device__ int   g_topk_idx[NASSIGN];
__device__ float g_topk_w[NASSIGN];
__device__ int   g_assign_tok[NASSIGN];
__device__ int   g_pos_of[NASSIGN];

__device__ __align__(16) __nv_bfloat16 g_xhi[NTOK * HD];
__device__ __align__(16) __nv_bfloat16 g_xlo[NTOK * HD];
__device__ __align__(16) __nv_bfloat16 g_Wihi[NEXP * FD * HD];
__device__ __align__(16) __nv_bfloat16 g_Wilo[NEXP * FD * HD];
__device__ __align__(16) __nv_bfloat16 g_Wohi[NEXP * HD * FD];
__device__ __align__(16) __nv_bfloat16 g_Wolo[NEXP * HD * FD];
__device__ __align__(16) __nv_bfloat16 g_hhi[(size_t)NASSIGN * FD];
__device__ __align__(16) __nv_bfloat16 g_hlo[(size_t)NASSIGN * FD];
__device__ __align__(16) float         g_buf2[(size_t)NASSIGN * HD];

// ---------------- PTX helpers -------------------------------------------------
__device__ __forceinline__ uint32_t smem_to_u32(const void* p) {
    uint32_t a;
    asm("{ .reg .u64 t; cvta.to.shared.u64 t, %1; cvt.u32.u64 %0, t; }" : "=r"(a) : "l"(p));
    return a;
}
__device__ __forceinline__ void cp16(uint32_t dst, const void* src, int sz) {
    asm volatile("cp.async.cg.shared.global [%0], [%1], 16, %2;"
                 :: "r"(dst), "l"(src), "r"(sz) : "memory");
}
#define CP_COMMIT() asm volatile("cp.async.commit_group;" ::: "memory")
#define CP_WAIT0()  asm volatile("cp.async.wait_group 0;" ::: "memory")
#define CP_WAIT1()  asm volatile("cp.async.wait_group 1;" ::: "memory")

#define LDSM4(r0, r1, r2, r3, addr) \
    asm volatile("ldmatrix.sync.aligned.m8n8.x4.shared.b16 {%0,%1,%2,%3}, [%4];" \
                 : "=r"(r0), "=r"(r1), "=r"(r2), "=r"(r3) : "r"(addr))

__device__ __forceinline__ void mma16816(float* d, const uint32_t* a, const uint32_t* b) {
    asm volatile(
        "mma.sync.aligned.m16n8k16.row.col.f32.bf16.bf16.f32 "
        "{%0,%1,%2,%3}, {%4,%5,%6,%7}, {%8,%9}, {%0,%1,%2,%3};"
        : "+f"(d[0]), "+f"(d[1]), "+f"(d[2]), "+f"(d[3])
        : "r"(a[0]), "r"(a[1]), "r"(a[2]), "r"(a[3]), "r"(b[0]), "r"(b[1]));
}

// ---------------- fp32 -> (bf16 hi, bf16 lo) split ---------------------------
// ZERO=true additionally zeroes the routing counters (ordered before router).
template <bool ZERO>
__global__ void split_kernel(const float4* __restrict__ src,
                             __nv_bfloat162* __restrict__ hi,
                             __nv_bfloat162* __restrict__ lo, int n4) {
    if (ZERO && blockIdx.x == 0 && threadIdx.x < NEXP) {
        g_counts[threadIdx.x] = 0;
        g_relcur[threadIdx.x] = 0;
    }
    int i = blockIdx.x * blockDim.x + threadIdx.x;
    if (i >= n4) return;
    float4 v = src[i];
    __nv_bfloat16 h0 = __float2bfloat16(v.x), h1 = __float2bfloat16(v.y);
    __nv_bfloat16 h2 = __float2bfloat16(v.z), h3 = __float2bfloat16(v.w);
    __nv_bfloat16 l0 = __float2bfloat16(v.x - __bfloat162float(h0));
    __nv_bfloat16 l1 = __float2bfloat16(v.y - __bfloat162float(h1));
    __nv_bfloat16 l2 = __float2bfloat16(v.z - __bfloat162float(h2));
    __nv_bfloat16 l3 = __float2bfloat16(v.w - __bfloat162float(h3));
    hi[2 * i]     = __halves2bfloat162(h0, h1);
    hi[2 * i + 1] = __halves2bfloat162(h2, h3);
    lo[2 * i]     = __halves2bfloat162(l0, l1);
    lo[2 * i + 1] = __halves2bfloat162(l2, l3);
}

// ---------------- Router ------------------------------------------------------
__global__ void router_kernel(const float* __restrict__ x, const float* __restrict__ Wr) {
    __shared__ float sWr[NEXP * HD];
    int tid = threadIdx.x;
    for (int i = tid; i < NEXP * HD; i += blockDim.x) sWr[i] = Wr[i];
    __syncthreads();

    int warp = tid >> 5, lane = tid & 31;
    int t = blockIdx.x * (blockDim.x >> 5) + warp;
    if (t >= NTOK) return;

    const float* xr = x + (size_t)t * HD;
    float acc[NEXP];
#pragma unroll
    for (int e = 0; e < NEXP; e++) acc[e] = 0.f;
    for (int h = lane; h < HD; h += 32) {
        float xv = xr[h];
#pragma unroll
        for (int e = 0; e < NEXP; e++) acc[e] = fmaf(xv, sWr[e * HD + h], acc[e]);
    }
#pragma unroll
    for (int e = 0; e < NEXP; e++)
#pragma unroll
        for (int o = 16; o > 0; o >>= 1) acc[e] += __shfl_xor_sync(0xFFFFFFFFu, acc[e], o);

    if (lane == 0) {
        int i0 = 0; float v0 = acc[0];
#pragma unroll
        for (int e = 1; e < NEXP; e++) if (acc[e] > v0) { v0 = acc[e]; i0 = e; }
        int i1 = -1; float v1 = -3.4e38f;
#pragma unroll
        for (int e = 0; e < NEXP; e++) if (e != i0 && acc[e] > v1) { v1 = acc[e]; i1 = e; }
        float z = expf(v1 - v0);
        float inv = 1.f / (1.f + z);
        g_topk_idx[2 * t] = i0;     g_topk_idx[2 * t + 1] = i1;
        g_topk_w[2 * t] = inv;      g_topk_w[2 * t + 1] = z * inv;
        atomicAdd(&g_counts[i0], 1);
        atomicAdd(&g_counts[i1], 1);
    }
}

// ---------------- Fill (computes segment base from counts inline) ------------
__global__ void fill_kernel() {
    int i = blockIdx.x * blockDim.x + threadIdx.x;
    if (i >= NASSIGN) return;
    int e = g_topk_idx[i];
    int base = 0;
#pragma unroll
    for (int j = 0; j < NEXP; j++) base += (j < e) ? g_counts[j] : 0;
    int pos = base + atomicAdd(&g_relcur[e], 1);
    g_assign_tok[pos] = i >> 1;
    g_pos_of[i] = pos;
}

// ---------------- HMMA grouped GEMM (fused 3-pass) ----------------------------
// C[128, 128] fp32 = A_hi@B_hi + A_hi@B_lo + A_lo@B_hi, all passes fused into
// one K loop: each k-tile stage holds 4 tiles (Ah, Al, Bh, Bl; 64KB), 3-stage
// cp.async pipeline (192KB smem), 8 warps (2x4), mma.sync.m16n8k16 bf16.
#define STAGE_BYTES 65536
#define NSTAGE 3
#define GEMM_SMEM_BYTES (STAGE_BYTES * NSTAGE)

template <bool FIRST>
__global__ void __launch_bounds__(256, 1)
moe_hmma_kernel(const float* __restrict__ bias) {
    constexpr int KD = FIRST ? HD : FD;
    constexpr int ND = FIRST ? FD : HD;
    constexpr int BK = 64;
    constexpr int NKT = KD / BK;

    extern __shared__ char smem[];
    const uint32_t sbase = smem_to_u32(smem);
    __shared__ int s_e, s_rowBase, s_segStart, s_nRows, s_valid;

    const int tid = threadIdx.x;
    const int wid = tid >> 5, lane = tid & 31;

    // ---- per-CTA tile mapping from expert counts ----
    if (tid == 0) {
        int accum = 0, nt = 0, fe = -1, fr = 0, fs = 0, fn = 0;
#pragma unroll
        for (int e = 0; e < NEXP; e++) {
            int c = g_counts[e];
            int te = (c + 127) >> 7;
            if (fe < 0 && (int)blockIdx.y < nt + te) {
                fe = e; fr = ((int)blockIdx.y - nt) * 128; fs = accum; fn = c;
            }
            nt += te; accum += c;
        }
        s_e = fe; s_rowBase = fr; s_segStart = fs; s_nRows = fn; s_valid = (fe >= 0);
    }
    __syncthreads();
    if (!s_valid) return;
    const int e = s_e, rowBase = s_rowBase, segStart = s_segStart, nRows = s_nRows;
    const int colBase = blockIdx.x * 128;

    // ---- cp.async load addressing: thread -> (row = tid/2, half = tid&1) ----
    const int lrow = tid >> 1;
    const int half = tid & 1;
    bool av;
    const __nv_bfloat16 *aHiP, *aLoP, *bHiP, *bLoP;
    {
        int r = rowBase + lrow;
        av = r < nRows;
        size_t arow = 0;
        if (av) arow = FIRST ? (size_t)g_assign_tok[segStart + r] : (size_t)(segStart + r);
        size_t aoff = arow * KD;
        aHiP = (FIRST ? g_xhi : g_hhi) + aoff;
        aLoP = (FIRST ? g_xlo : g_hlo) + aoff;
        size_t brow = ((size_t)e * ND + colBase + lrow) * KD;
        bHiP = (FIRST ? g_Wihi : g_Wohi) + brow;
        bLoP = (FIRST ? g_Wilo : g_Wolo) + brow;
    }
    uint32_t dstOff[4];
    {
        const uint32_t rmask = (lrow & 7) << 4;
#pragma unroll
        for (int i = 0; i < 4; i++) {
            uint32_t kb = (uint32_t)(half * 4 + i) * 16;
            dstOff[i] = (uint32_t)lrow * 128 + (kb ^ rmask);
        }
    }
    const int aSz = av ? 16 : 0;

    auto load_stage = [&](int buf, int kt) {
        const char* ahS = (const char*)(aHiP + kt * BK) + half * 64;
        const char* alS = (const char*)(aLoP + kt * BK) + half * 64;
        const char* bhS = (const char*)(bHiP + kt * BK) + half * 64;
        const char* blS = (const char*)(bLoP + kt * BK) + half * 64;
        const uint32_t S = sbase + buf * STAGE_BYTES;
#pragma unroll
        for (int i = 0; i < 4; i++) cp16(S +         dstOff[i], ahS + i * 16, aSz);
#pragma unroll
        for (int i = 0; i < 4; i++) cp16(S + 16384 + dstOff[i], alS + i * 16, aSz);
#pragma unroll
        for (int i = 0; i < 4; i++) cp16(S + 32768 + dstOff[i], bhS + i * 16, 16);
#pragma unroll
        for (int i = 0; i < 4; i++) cp16(S + 49152 + dstOff[i], blS + i * 16, 16);
        CP_COMMIT();
    };

    // ---- ldmatrix addressing (per warp): 2x4 warps, tile 64x32 ----
    const int warpM = (wid & 1) * 64;
    const int warpN = (wid >> 1) * 32;

    uint32_t aRowB[4], aMask[4];
#pragma unroll
    for (int mi = 0; mi < 4; mi++) {
        int row = warpM + mi * 16 + (lane & 7) + ((lane >> 3) & 1) * 8;
        aRowB[mi] = (uint32_t)row * 128;
        aMask[mi] = (uint32_t)(row & 7) << 4;
    }
    const uint32_t aKadd = ((lane >> 4) & 1) * 16;

    uint32_t bRowB[2], bMask[2];
#pragma unroll
    for (int np = 0; np < 2; np++) {
        int row = warpN + np * 16 + (lane & 7) + ((lane >> 4) & 1) * 8;
        bRowB[np] = (uint32_t)row * 128;
        bMask[np] = (uint32_t)(row & 7) << 4;
    }
    const uint32_t bKadd = ((lane >> 3) & 1) * 16;

    float acc[4][4][4];
#pragma unroll
    for (int mi = 0; mi < 4; mi++)
#pragma unroll
        for (int ni = 0; ni < 4; ni++)
#pragma unroll
            for (int k = 0; k < 4; k++) acc[mi][ni][k] = 0.f;

    // ---- 3-stage pipelined mainloop ----
    load_stage(0, 0);
    load_stage(1, 1);
    for (int kt = 0; kt < NKT; ++kt) {
        if (kt + 1 < NKT) CP_WAIT1(); else CP_WAIT0();
        __syncthreads();
        if (kt + 2 < NKT) load_stage((kt + 2) % NSTAGE, kt + 2);

        const uint32_t S = sbase + (kt % NSTAGE) * STAGE_BYTES;
#pragma unroll
        for (int kk = 0; kk < 4; kk++) {
            const uint32_t kbyte = (uint32_t)kk * 32;
            uint32_t ah[4][4], al[4][4], bh[2][4], bl[2][4];
#pragma unroll
            for (int mi = 0; mi < 4; mi++)
                LDSM4(ah[mi][0], ah[mi][1], ah[mi][2], ah[mi][3],
                      S + aRowB[mi] + ((kbyte + aKadd) ^ aMask[mi]));
#pragma unroll
            for (int np = 0; np < 2; np++)
                LDSM4(bh[np][0], bh[np][1], bh[np][2], bh[np][3],
                      S + 32768 + bRowB[np] + ((kbyte + bKadd) ^ bMask[np]));
            // pass 0: Ah @ Bh
#pragma unroll
            for (int mi = 0; mi < 4; mi++)
#pragma unroll
                for (int ni = 0; ni < 4; ni++)
                    mma16816(acc[mi][ni], ah[mi], &bh[ni >> 1][2 * (ni & 1)]);
#pragma unroll
            for (int np = 0; np < 2; np++)
                LDSM4(bl[np][0], bl[np][1], bl[np][2], bl[np][3],
                      S + 49152 + bRowB[np] + ((kbyte + bKadd) ^ bMask[np]));
            // pass 1: Ah @ Bl
#pragma unroll
            for (int mi = 0; mi < 4; mi++)
#pragma unroll
                for (int ni = 0; ni < 4; ni++)
                    mma16816(acc[mi][ni], ah[mi], &bl[ni >> 1][2 * (ni & 1)]);
#pragma unroll
            for (int mi = 0; mi < 4; mi++)
                LDSM4(al[mi][0], al[mi][1], al[mi][2], al[mi][3],
                      S + 16384 + aRowB[mi] + ((kbyte + aKadd) ^ aMask[mi]));
            // pass 2: Al @ Bh
#pragma unroll
            for (int mi = 0; mi < 4; mi++)
#pragma unroll
                for (int ni = 0; ni < 4; ni++)
                    mma16816(acc[mi][ni], al[mi], &bh[ni >> 1][2 * (ni & 1)]);
        }
        __syncthreads();
    }

    // ---- epilogue: bias (+GELU+split for GEMM1) ------------------------------
    const float* bE = bias + (size_t)e * ND + colBase;
    const int qrow = lane >> 2;
    const int qcol = 2 * (lane & 3);
#pragma unroll
    for (int mi = 0; mi < 4; mi++) {
#pragma unroll
        for (int half2 = 0; half2 < 2; half2++) {
            int row = rowBase + warpM + mi * 16 + qrow + half2 * 8;
            if (row >= nRows) continue;
            size_t orow = (size_t)segStart + row;
#pragma unroll
            for (int ni = 0; ni < 4; ni++) {
                int col = colBase + warpN + ni * 8 + qcol;
                float v0 = acc[mi][ni][2 * half2]     + bE[warpN + ni * 8 + qcol];
                float v1 = acc[mi][ni][2 * half2 + 1] + bE[warpN + ni * 8 + qcol + 1];
                if (FIRST) {
                    v0 = 0.5f * v0 * (1.f + erff(v0 * 0.70710678118654752f));
                    v1 = 0.5f * v1 * (1.f + erff(v1 * 0.70710678118654752f));
                    __nv_bfloat16 h0 = __float2bfloat16(v0);
                    __nv_bfloat16 h1 = __float2bfloat16(v1);
                    __nv_bfloat16 l0 = __float2bfloat16(v0 - __bfloat162float(h0));
                    __nv_bfloat16 l1 = __float2bfloat16(v1 - __bfloat162float(h1));
                    *(__nv_bfloat162*)(g_hhi + orow * FD + col) = __halves2bfloat162(h0, h1);
                    *(__nv_bfloat162*)(g_hlo + orow * FD + col) = __halves2bfloat162(l0, l1);
                } else {
                    float2 o = make_float2(v0, v1);
                    *(float2*)(g_buf2 + orow * HD + col) = o;
                }
            }
        }
    }
}

// ---------------- Combine -----------------------------------------------------
__global__ void combine_kernel(float* __restrict__ out) {
    const int HV = HD / 4;
    int idx = blockIdx.x * blockDim.x + threadIdx.x;
    if (idx >= NTOK * HV) return;
    int t = idx / HV;
    int h4 = (idx - t * HV) * 4;
    float w0 = g_topk_w[2 * t], w1 = g_topk_w[2 * t + 1];
    int p0 = g_pos_of[2 * t], p1 = g_pos_of[2 * t + 1];
    float4 a = *(const float4*)&g_buf2[(size_t)p0 * HD + h4];
    float4 b = *(const float4*)&g_buf2[(size_t)p1 * HD + h4];
    float4 o;
    o.x = w0 * a.x + w1 * b.x;
    o.y = w0 * a.y + w1 * b.y;
    o.z = w0 * a.z + w1 * b.z;
    o.w = w0 * a.w + w1 * b.w;
    *(float4*)&out[(size_t)t * HD + h4] = o;
}

// ---------------- Launch ------------------------------------------------------
extern "C" void kernel_launch(void* const* d_in, const int* in_sizes, int n_in,
                              void* d_out, int out_size) {
    const float* x  = (const float*)d_in[0];   // [8192, 768]
    const float* Wr = (const float*)d_in[1];   // [8, 768]
    const float* Wi = (const float*)d_in[2];   // [8, 3072, 768]
    const float* bi = (const float*)d_in[3];   // [8, 3072]
    const float* Wo = (const float*)d_in[4];   // [8, 768, 3072]
    const float* bo = (const float*)d_in[5];   // [8, 768]
    float* out = (float*)d_out;                // [8192, 768]

    cudaFuncSetAttribute(moe_hmma_kernel<true>,
                         cudaFuncAttributeMaxDynamicSharedMemorySize, GEMM_SMEM_BYTES);
    cudaFuncSetAttribute(moe_hmma_kernel<false>,
                         cudaFuncAttributeMaxDynamicSharedMemorySize, GEMM_SMEM_BYTES);

    __nv_bfloat16 *p_xhi, *p_xlo, *p_Wihi, *p_Wilo, *p_Wohi, *p_Wolo;
    cudaGetSymbolAddress((void**)&p_xhi,  g_xhi);
    cudaGetSymbolAddress((void**)&p_xlo,  g_xlo);
    cudaGetSymbolAddress((void**)&p_Wihi, g_Wihi);
    cudaGetSymbolAddress((void**)&p_Wilo, g_Wilo);
    cudaGetSymbolAddress((void**)&p_Wohi, g_Wohi);
    cudaGetSymbolAddress((void**)&p_Wolo, g_Wolo);

    // Launch order places gemm1 at index 4, gemm2 at index 6 (ncu capture window)
    int n4x = NTOK * HD / 4;
    split_kernel<true><<<(n4x + 255) / 256, 256>>>((const float4*)x,
        (__nv_bfloat162*)p_xhi, (__nv_bfloat162*)p_xlo, n4x);          // 0 (also zeroes counters)
    int n4w = NEXP * FD * HD / 4;
    split_kernel<false><<<(n4w + 255) / 256, 256>>>((const float4*)Wi,
        (__nv_bfloat162*)p_Wihi, (__nv_bfloat162*)p_Wilo, n4w);        // 1
    router_kernel<<<NTOK / 8, 256>>>(x, Wr);                           // 2
    fill_kernel<<<(NASSIGN + 255) / 256, 256>>>();                     // 3
    {   // 4: GEMM1 [rows, 768] @ Wi^T -> h (GELU + hi/lo bf16 split)
        dim3 grid(FD / 128, 136, 1);
        moe_hmma_kernel<true><<<grid, 256, GEMM_SMEM_BYTES>>>(bi);
    }
    split_kernel<false><<<(n4w + 255) / 256, 256>>>((const float4*)Wo,
        (__nv_bfloat162*)p_Wohi, (__nv_bfloat162*)p_Wolo, n4w);        // 5
    {   // 6: GEMM2 [rows, 3072] @ Wo^T -> g_buf2 (fp32)
        dim3 grid(HD / 128, 136, 1);
        moe_hmma_kernel<false><<<grid, 256, GEMM_SMEM_BYTES>>>(bo);
    }
    combine_kernel<<<(NTOK * (HD / 4) + 255) / 256, 256>>>(out);       // 7
}